// round 2
// baseline (speedup 1.0000x reference)
#include <cuda_runtime.h>
#include <math.h>

#define B 32
#define HH 512
#define WW 512
#define NPIX (HH*WW)          // 262144
#define NTOT (B*NPIX)         // 8388608
#define KRAD 15               // box radius
#define KSZ 31

// Scratch: horizontal box sums of y_target. 33.5 MB.
__device__ float g_Hsum[NTOT];

// Accumulators
__device__ float g_sum_t[B];
__device__ float g_sum_p[B];
__device__ float g_wsum[B];
__device__ float g_inter[B];
__device__ float g_uni[B];
__device__ float g_qsum[B];
__device__ float g_bce;

__global__ void k_zero() {
    int i = threadIdx.x;
    if (i < B) {
        g_sum_t[i] = 0.f; g_sum_p[i] = 0.f;
        g_wsum[i]  = 0.f; g_inter[i] = 0.f;
        g_uni[i]   = 0.f; g_qsum[i]  = 0.f;
    }
    if (i == 0) g_bce = 0.f;
}

// -------- Pass A: horizontal box sum + per-image sum_t, sum_p, global bce ----
// 8 warps per block, one warp per row. 2048 blocks cover 16384 rows.
__global__ __launch_bounds__(256) void k_passA(const float* __restrict__ P,
                                               const float* __restrict__ T) {
    __shared__ __align__(16) float sIn[8][WW];
    __shared__ __align__(16) float sOut[8][WW];
    __shared__ float red[3][8];

    const int warp = threadIdx.x >> 5;
    const int lane = threadIdx.x & 31;
    const int rowg = blockIdx.x * 8 + warp;          // global row 0..16383
    const int b    = blockIdx.x >> 6;                // 64 blocks per image

    const float4* t4 = (const float4*)(T + (size_t)rowg * WW);
    const float4* p4 = (const float4*)(P + (size_t)rowg * WW);

    float lsum_t = 0.f, lsum_p = 0.f, lbce = 0.f;
    #pragma unroll
    for (int i = 0; i < 4; i++) {
        float4 tv = t4[lane + 32*i];
        float4 pv = p4[lane + 32*i];
        ((float4*)sIn[warp])[lane + 32*i] = tv;
        float ts[4] = {tv.x, tv.y, tv.z, tv.w};
        float xs[4] = {pv.x, pv.y, pv.z, pv.w};
        #pragma unroll
        for (int k = 0; k < 4; k++) {
            float t = ts[k], x = xs[k];
            lsum_t += t;
            lsum_p += 1.f / (1.f + expf(-x));
            // stable BCE-with-logits: max(x,0) - x*t + log1p(exp(-|x|))
            lbce   += fmaxf(x, 0.f) - x * t + log1pf(expf(-fabsf(x)));
        }
    }
    __syncwarp();

    // per-lane sliding window over 16 contiguous columns
    const int base = lane * 16;
    float s = 0.f;
    #pragma unroll
    for (int k = base - KRAD; k <= base + KRAD; k++)
        if (k >= 0 && k < WW) s += sIn[warp][k];
    sOut[warp][base] = s;
    #pragma unroll
    for (int j = 1; j < 16; j++) {
        int ka = base + KRAD + j;
        int kr = base - KRAD - 1 + j;
        if (ka < WW) s += sIn[warp][ka];
        if (kr >= 0) s -= sIn[warp][kr];
        sOut[warp][base + j] = s;
    }
    __syncwarp();

    float4* h4 = (float4*)(g_Hsum + (size_t)rowg * WW);
    #pragma unroll
    for (int i = 0; i < 4; i++)
        h4[lane + 32*i] = ((float4*)sOut[warp])[lane + 32*i];

    // block reduce the three scalars, one atomic each
    #pragma unroll
    for (int o = 16; o > 0; o >>= 1) {
        lsum_t += __shfl_xor_sync(~0u, lsum_t, o);
        lsum_p += __shfl_xor_sync(~0u, lsum_p, o);
        lbce   += __shfl_xor_sync(~0u, lbce,   o);
    }
    if (lane == 0) { red[0][warp] = lsum_t; red[1][warp] = lsum_p; red[2][warp] = lbce; }
    __syncthreads();
    if (threadIdx.x == 0) {
        float a = 0.f, c = 0.f, d = 0.f;
        #pragma unroll
        for (int w = 0; w < 8; w++) { a += red[0][w]; c += red[1][w]; d += red[2][w]; }
        atomicAdd(&g_sum_t[b], a);
        atomicAdd(&g_sum_p[b], c);
        atomicAdd(&g_bce, d);
    }
}

// -------- Pass B: vertical box (running window) + weighted sums + E-measure --
// grid 512 blocks: b = bx>>4, band = (bx>>2)&3, strip = bx&3. 128 threads = cols.
__global__ __launch_bounds__(128) void k_passB(const float* __restrict__ P,
                                               const float* __restrict__ T) {
    __shared__ float red[4][4];
    const int bx    = blockIdx.x;
    const int b     = bx >> 4;
    const int band  = (bx >> 2) & 3;
    const int strip = bx & 3;
    const int col   = strip * 128 + threadIdx.x;
    const int r0    = band * 128;

    const float* Hb = g_Hsum + (size_t)b * NPIX;
    const float* Tb = T + (size_t)b * NPIX;
    const float* Pb = P + (size_t)b * NPIX;

    const float mean_p = g_sum_p[b] * (1.f / (float)NPIX);
    const float mean_t = g_sum_t[b] * (1.f / (float)NPIX);

    float vsum = 0.f;
    for (int r = r0 - KRAD; r <= r0 + KRAD; r++)
        if (r >= 0 && r < HH) vsum += Hb[r * WW + col];

    float a_w = 0.f, a_i = 0.f, a_u = 0.f, a_q = 0.f;
    for (int r = r0; r < r0 + 128; r++) {
        float box = vsum * (1.f / 961.f);
        float t = Tb[r * WW + col];
        float x = Pb[r * WW + col];
        float p = 1.f / (1.f + expf(-x));
        float w = 1.f + 5.f * fabsf(box - t);
        a_w += w;
        a_i += p * t * w;
        a_u += (p + t) * w;
        float fp = p - mean_p;
        float ft = t - mean_t;
        float efm = (2.f * fp * ft + 1e-8f) / (fp * fp + ft * ft + 1e-8f);
        float q = 1.f + efm;
        a_q += q * q * 0.25f;
        int ra = r + KRAD + 1, rr = r - KRAD;
        if (ra < HH) vsum += Hb[ra * WW + col];
        if (rr >= 0) vsum -= Hb[rr * WW + col];
    }

    const int warp = threadIdx.x >> 5, lane = threadIdx.x & 31;
    #pragma unroll
    for (int o = 16; o > 0; o >>= 1) {
        a_w += __shfl_xor_sync(~0u, a_w, o);
        a_i += __shfl_xor_sync(~0u, a_i, o);
        a_u += __shfl_xor_sync(~0u, a_u, o);
        a_q += __shfl_xor_sync(~0u, a_q, o);
    }
    if (lane == 0) { red[0][warp] = a_w; red[1][warp] = a_i; red[2][warp] = a_u; red[3][warp] = a_q; }
    __syncthreads();
    if (threadIdx.x == 0) {
        float rw = 0.f, ri = 0.f, ru = 0.f, rq = 0.f;
        #pragma unroll
        for (int w = 0; w < 4; w++) { rw += red[0][w]; ri += red[1][w]; ru += red[2][w]; rq += red[3][w]; }
        atomicAdd(&g_wsum[b],  rw);
        atomicAdd(&g_inter[b], ri);
        atomicAdd(&g_uni[b],   ru);
        atomicAdd(&g_qsum[b],  rq);
    }
}

// -------- Final: combine per-image losses into scalar ------------------------
__global__ void k_final(float* __restrict__ out) {
    const int b = threadIdx.x;  // 32 threads
    float bce = g_bce * (1.f / (float)NTOT);
    float ws  = g_wsum[b];
    float wbce = (ws * bce + 1e-8f) / (ws + 1e-8f);
    float in_  = g_inter[b];
    float un_  = g_uni[b];
    float wiou = 1.f - (in_ + 1.f + 1e-8f) / (un_ - in_ + 1.f + 1e-8f);
    float el   = 1.f - g_qsum[b] * (1.f / (float)NPIX);
    float v = wbce + wiou + el;
    #pragma unroll
    for (int o = 16; o > 0; o >>= 1) v += __shfl_xor_sync(~0u, v, o);
    if (b == 0) out[0] = v * (1.f / (float)B);
}

extern "C" void kernel_launch(void* const* d_in, const int* in_sizes, int n_in,
                              void* d_out, int out_size) {
    const float* y_pred   = (const float*)d_in[0];
    const float* y_target = (const float*)d_in[1];
    float* out = (float*)d_out;

    k_zero<<<1, 64>>>();
    k_passA<<<2048, 256>>>(y_pred, y_target);
    k_passB<<<512, 128>>>(y_pred, y_target);
    k_final<<<1, 32>>>(out);
}

// round 3
// speedup vs baseline: 1.9464x; 1.9464x over previous
#include <cuda_runtime.h>
#include <math.h>

#define B 32
#define HH 512
#define WW 512
#define NPIX (HH*WW)          // 262144
#define NTOT (B*NPIX)         // 8388608
#define KRAD 15               // box radius

// Scratch: horizontal box sums of y_target. 33.5 MB.
__device__ float g_Hsum[NTOT];

// Accumulators
__device__ float g_sum_t[B];
__device__ float g_sum_p[B];
__device__ float g_wsum[B];
__device__ float g_inter[B];
__device__ float g_uni[B];
__device__ float g_qsum[B];
__device__ float g_bce;

__global__ void k_zero() {
    int i = threadIdx.x;
    if (i < B) {
        g_sum_t[i] = 0.f; g_sum_p[i] = 0.f;
        g_wsum[i]  = 0.f; g_inter[i] = 0.f;
        g_uni[i]   = 0.f; g_qsum[i]  = 0.f;
    }
    if (i == 0) g_bce = 0.f;
}

__device__ __forceinline__ float fsigmoid(float x) {
    return __fdividef(1.f, 1.f + __expf(-x));
}

// -------- Pass A: horizontal box sum + per-image sum_t, sum_p, global bce ----
// 8 warps per block, one warp per row. 2048 blocks cover 16384 rows.
__global__ __launch_bounds__(256) void k_passA(const float* __restrict__ P,
                                               const float* __restrict__ T) {
    __shared__ __align__(16) float sIn[8][WW];
    __shared__ __align__(16) float sOut[8][WW];
    __shared__ float red[3][8];

    const int warp = threadIdx.x >> 5;
    const int lane = threadIdx.x & 31;
    const int rowg = blockIdx.x * 8 + warp;          // global row 0..16383
    const int b    = blockIdx.x >> 6;                // 64 blocks per image

    const float4* t4 = (const float4*)(T + (size_t)rowg * WW);
    const float4* p4 = (const float4*)(P + (size_t)rowg * WW);

    float lsum_t = 0.f, lsum_p = 0.f, lbce = 0.f;
    #pragma unroll
    for (int i = 0; i < 4; i++) {
        float4 tv = t4[lane + 32*i];
        float4 pv = p4[lane + 32*i];
        ((float4*)sIn[warp])[lane + 32*i] = tv;
        float ts[4] = {tv.x, tv.y, tv.z, tv.w};
        float xs[4] = {pv.x, pv.y, pv.z, pv.w};
        #pragma unroll
        for (int k = 0; k < 4; k++) {
            float t = ts[k], x = xs[k];
            lsum_t += t;
            lsum_p += fsigmoid(x);
            // stable BCE-with-logits: max(x,0) - x*t + log(1 + exp(-|x|))
            lbce   += fmaxf(x, 0.f) - x * t + __logf(1.f + __expf(-fabsf(x)));
        }
    }
    __syncwarp();

    // per-lane sliding window over 16 contiguous columns
    const int base = lane * 16;
    float s = 0.f;
    #pragma unroll
    for (int k = base - KRAD; k <= base + KRAD; k++)
        if (k >= 0 && k < WW) s += sIn[warp][k];
    sOut[warp][base] = s;
    #pragma unroll
    for (int j = 1; j < 16; j++) {
        int ka = base + KRAD + j;
        int kr = base - KRAD - 1 + j;
        if (ka < WW) s += sIn[warp][ka];
        if (kr >= 0) s -= sIn[warp][kr];
        sOut[warp][base + j] = s;
    }
    __syncwarp();

    float4* h4 = (float4*)(g_Hsum + (size_t)rowg * WW);
    #pragma unroll
    for (int i = 0; i < 4; i++)
        h4[lane + 32*i] = ((float4*)sOut[warp])[lane + 32*i];

    // block reduce the three scalars, one atomic each
    #pragma unroll
    for (int o = 16; o > 0; o >>= 1) {
        lsum_t += __shfl_xor_sync(~0u, lsum_t, o);
        lsum_p += __shfl_xor_sync(~0u, lsum_p, o);
        lbce   += __shfl_xor_sync(~0u, lbce,   o);
    }
    if (lane == 0) { red[0][warp] = lsum_t; red[1][warp] = lsum_p; red[2][warp] = lbce; }
    __syncthreads();
    if (threadIdx.x == 0) {
        float a = 0.f, c = 0.f, d = 0.f;
        #pragma unroll
        for (int w = 0; w < 8; w++) { a += red[0][w]; c += red[1][w]; d += red[2][w]; }
        atomicAdd(&g_sum_t[b], a);
        atomicAdd(&g_sum_p[b], c);
        atomicAdd(&g_bce, d);
    }
}

// -------- Pass B: vertical box (running window) + weighted sums + E-measure --
// grid 2048 blocks: b = bx>>6, band = (bx>>2)&15 (32 rows), strip = bx&3.
// 128 threads = one column each.
__global__ __launch_bounds__(128) void k_passB(const float* __restrict__ P,
                                               const float* __restrict__ T) {
    __shared__ float red[4][4];
    const int bx    = blockIdx.x;
    const int b     = bx >> 6;
    const int band  = (bx >> 2) & 15;
    const int strip = bx & 3;
    const int col   = strip * 128 + threadIdx.x;
    const int r0    = band * 32;

    const float* Hb = g_Hsum + (size_t)b * NPIX;
    const float* Tb = T + (size_t)b * NPIX;
    const float* Pb = P + (size_t)b * NPIX;

    const float mean_p = g_sum_p[b] * (1.f / (float)NPIX);
    const float mean_t = g_sum_t[b] * (1.f / (float)NPIX);

    // init vertical running window around r0
    float vsum = 0.f;
    {
        const int lo = max(r0 - KRAD, 0);
        const int hi = min(r0 + KRAD, HH - 1);
        for (int r = lo; r <= hi; r++) vsum += Hb[r * WW + col];
    }

    float a_w = 0.f, a_i = 0.f, a_u = 0.f, a_q = 0.f;
    #pragma unroll 4
    for (int r = r0; r < r0 + 32; r++) {
        float box = vsum * (1.f / 961.f);
        float t = Tb[r * WW + col];
        float x = Pb[r * WW + col];
        float p = fsigmoid(x);
        float w = 1.f + 5.f * fabsf(box - t);
        a_w += w;
        a_i += p * t * w;
        a_u += (p + t) * w;
        float fp = p - mean_p;
        float ft = t - mean_t;
        float efm = __fdividef(2.f * fp * ft + 1e-8f, fp * fp + ft * ft + 1e-8f);
        float q = 1.f + efm;
        a_q += q * q * 0.25f;
        int ra = r + KRAD + 1, rr = r - KRAD;
        if (ra < HH) vsum += Hb[ra * WW + col];
        if (rr >= 0) vsum -= Hb[rr * WW + col];
    }

    const int warp = threadIdx.x >> 5, lane = threadIdx.x & 31;
    #pragma unroll
    for (int o = 16; o > 0; o >>= 1) {
        a_w += __shfl_xor_sync(~0u, a_w, o);
        a_i += __shfl_xor_sync(~0u, a_i, o);
        a_u += __shfl_xor_sync(~0u, a_u, o);
        a_q += __shfl_xor_sync(~0u, a_q, o);
    }
    if (lane == 0) { red[0][warp] = a_w; red[1][warp] = a_i; red[2][warp] = a_u; red[3][warp] = a_q; }
    __syncthreads();
    if (threadIdx.x == 0) {
        float rw = 0.f, ri = 0.f, ru = 0.f, rq = 0.f;
        #pragma unroll
        for (int w = 0; w < 4; w++) { rw += red[0][w]; ri += red[1][w]; ru += red[2][w]; rq += red[3][w]; }
        atomicAdd(&g_wsum[b],  rw);
        atomicAdd(&g_inter[b], ri);
        atomicAdd(&g_uni[b],   ru);
        atomicAdd(&g_qsum[b],  rq);
    }
}

// -------- Final: combine per-image losses into scalar ------------------------
__global__ void k_final(float* __restrict__ out) {
    const int b = threadIdx.x;  // 32 threads
    float bce = g_bce * (1.f / (float)NTOT);
    float ws  = g_wsum[b];
    float wbce = (ws * bce + 1e-8f) / (ws + 1e-8f);
    float in_  = g_inter[b];
    float un_  = g_uni[b];
    float wiou = 1.f - (in_ + 1.f + 1e-8f) / (un_ - in_ + 1.f + 1e-8f);
    float el   = 1.f - g_qsum[b] * (1.f / (float)NPIX);
    float v = wbce + wiou + el;
    #pragma unroll
    for (int o = 16; o > 0; o >>= 1) v += __shfl_xor_sync(~0u, v, o);
    if (b == 0) out[0] = v * (1.f / (float)B);
}

extern "C" void kernel_launch(void* const* d_in, const int* in_sizes, int n_in,
                              void* d_out, int out_size) {
    const float* y_pred   = (const float*)d_in[0];
    const float* y_target = (const float*)d_in[1];
    float* out = (float*)d_out;

    k_zero<<<1, 64>>>();
    k_passA<<<2048, 256>>>(y_pred, y_target);
    k_passB<<<2048, 128>>>(y_pred, y_target);
    k_final<<<1, 32>>>(out);
}